// round 5
// baseline (speedup 1.0000x reference)
#include <cuda_runtime.h>
#include <math.h>

// GeneralMaxValPool: segment-argmax pooling over COO remap.
// B=4, OLD=262144, NEW=65536, V=64, nnz=262144, BV=256.
// Single fused kernel: per-block binary search for segment bounds,
// float4 gathers, float4 index stores.

#define OLDN 262144
#define NEWN 65536
#define BB   4
#define VV   64
#define BVN  256
#define NNZ  262144
#define SEGS 16          // segments per block
#define SG   4           // segments per 64-thread group (SEGS/4)
#define PITCH 257        // shared pitch for srow
#define CAPG 128         // per-group (n|sid, w) capacity (mean ~16, >30 sigma)
#define UF   4           // float4 loads in flight per thread (64B)
#define SENT 1023        // sentinel sid

__global__ void __launch_bounds__(256, 4)
pool_kernel(const float* __restrict__ x,
            const float* __restrict__ weights,
            const int*   __restrict__ row,
            const int*   __restrict__ col,
            float* __restrict__ out)
{
    __shared__ int2 s_pk[4 * CAPG];          // per group: (n | sid<<20, w-bits)
    __shared__ int  srow[SEGS * PITCH];
    __shared__ int  s_start[SEGS + 1];

    const int s0 = blockIdx.x * SEGS;
    const int t  = threadIdx.x;
    const int g  = t >> 6;        // group 0..3
    const int l  = t & 63;        // lane in group
    const int b  = l >> 4;        // 0..3
    const int v4 = l & 15;        // float4 column, v = v4*4..v4*4+3

    // Per-block segment boundaries via binary search on sorted dense `row`.
    // start(s) = lower_bound(row, s); bounded in [s, NNZ-(NEWN-s)].
    if (t <= SEGS) {
        const int s = s0 + t;
        if (s >= NEWN) {
            s_start[t] = NNZ;
        } else {
            int lo = s, hi = NNZ - (NEWN - s);
            while (lo < hi) {
                const int mid = (lo + hi) >> 1;
                if (__ldg(&row[mid]) < s) lo = mid + 1; else hi = mid;
            }
            s_start[t] = lo;
        }
    }
    __syncthreads();

    const int sg0  = g * SG;
    const int gi0  = s_start[sg0];
    const int gcnt = s_start[sg0 + SG] - gi0;
    const bool fits = (gcnt <= CAPG);

    // Fill packed (n|sid, w) per group; per-segment loops avoid cross-pass races.
    if (fits) {
        int2* pk = s_pk + g * CAPG;
        for (int sl = 0; sl < SG; ++sl) {
            const int a = s_start[sg0 + sl];
            const int e = s_start[sg0 + sl + 1];
            for (int i = a + l; i < e; i += 64) {
                int2 p;
                p.x = col[i] | ((sg0 + sl) << 20);
                p.y = __float_as_int(weights[i]);
                pk[i - gi0] = p;
            }
        }
        const int np = (gcnt + UF - 1) / UF * UF;
        for (int j = gcnt + l; j < np; j += 64) {
            pk[j] = make_int2(SENT << 20, 0);
        }
    }
    __syncthreads();

    const float4* xb4 = (const float4*)(x + (size_t)b * (OLDN * VV)) + v4;
    const size_t out_val_base = ((size_t)b * (NEWN * VV) + (size_t)s0 * VV) / 4 + v4;
    float4* out4 = (float4*)out;

    if (fits) {
        const int2* pk = s_pk + g * CAPG;
        const int np = (gcnt + UF - 1) / UF * UF;
        float  bw[4] = {-INFINITY, -INFINITY, -INFINITY, -INFINITY};
        float4 bv = make_float4(0.f, 0.f, 0.f, 0.f);
        int    bn[4] = {0, 0, 0, 0};
        int    cursid = sg0;
        for (int base = 0; base < np; base += UF) {
            int2   p[UF];
            float4 pv[UF];
            #pragma unroll
            for (int u = 0; u < UF; ++u) p[u] = pk[base + u];      // LDS.64 broadcast
            #pragma unroll
            for (int u = 0; u < UF; ++u)                            // UF LDG.128 in flight
                pv[u] = __ldg(&xb4[(p[u].x & 0xFFFFF) * (VV / 4)]);
            #pragma unroll
            for (int u = 0; u < UF; ++u) {
                const int sid = ((unsigned)p[u].x) >> 20;           // uniform across group
                if (sid != cursid) {
                    if (cursid < SEGS) {
                        out4[out_val_base + (size_t)cursid * (VV / 4)] = bv;
                        const int sb = cursid * PITCH + b * 64 + v4 * 4;
                        srow[sb + 0] = bn[0]; srow[sb + 1] = bn[1];
                        srow[sb + 2] = bn[2]; srow[sb + 3] = bn[3];
                    }
                    cursid = sid;
                    bw[0] = bw[1] = bw[2] = bw[3] = -INFINITY;
                    bv = make_float4(0.f, 0.f, 0.f, 0.f);
                    bn[0] = bn[1] = bn[2] = bn[3] = 0;
                }
                const float w = __int_as_float(p[u].y);
                const int   n = p[u].x & 0xFFFFF;
                float wv;
                wv = w * pv[u].x; if (wv > bw[0]) { bw[0] = wv; bv.x = pv[u].x; bn[0] = n; }
                wv = w * pv[u].y; if (wv > bw[1]) { bw[1] = wv; bv.y = pv[u].y; bn[1] = n; }
                wv = w * pv[u].z; if (wv > bw[2]) { bw[2] = wv; bv.z = pv[u].z; bn[2] = n; }
                wv = w * pv[u].w; if (wv > bw[3]) { bw[3] = wv; bv.w = pv[u].w; bn[3] = n; }
            }
        }
        if (cursid < SEGS) {
            out4[out_val_base + (size_t)cursid * (VV / 4)] = bv;
            const int sb = cursid * PITCH + b * 64 + v4 * 4;
            srow[sb + 0] = bn[0]; srow[sb + 1] = bn[1];
            srow[sb + 2] = bn[2]; srow[sb + 3] = bn[3];
        }
    } else {
        // ---- slow fallback (statistically never taken) ----
        for (int sl = sg0; sl < sg0 + SG; ++sl) {
            float  bw[4] = {-INFINITY, -INFINITY, -INFINITY, -INFINITY};
            float4 bv = make_float4(0.f, 0.f, 0.f, 0.f);
            int    bn[4] = {0, 0, 0, 0};
            for (int i = s_start[sl]; i < s_start[sl + 1]; ++i) {
                const int    n  = __ldg(&col[i]);
                const float  w  = __ldg(&weights[i]);
                const float4 pv = __ldg(&xb4[n * (VV / 4)]);
                float wv;
                wv = w * pv.x; if (wv > bw[0]) { bw[0] = wv; bv.x = pv.x; bn[0] = n; }
                wv = w * pv.y; if (wv > bw[1]) { bw[1] = wv; bv.y = pv.y; bn[1] = n; }
                wv = w * pv.z; if (wv > bw[2]) { bw[2] = wv; bv.z = pv.z; bn[2] = n; }
                wv = w * pv.w; if (wv > bw[3]) { bw[3] = wv; bv.w = pv.w; bn[3] = n; }
            }
            out4[out_val_base + (size_t)sl * (VV / 4)] = bv;
            const int sb = sl * PITCH + b * 64 + v4 * 4;
            srow[sb + 0] = bn[0]; srow[sb + 1] = bn[1];
            srow[sb + 2] = bn[2]; srow[sb + 3] = bn[3];
        }
    }
    __syncthreads();

    // Phase 2: nnz_ind as float4 stores. out[OFF1 + c*NEW + s] = argmax node,
    // out[OFF2 + ...] = c. Thread writes 4 consecutive s (16B) per iter.
    const size_t OFF1_4 = ((size_t)BB * NEWN * VV) / 4;        // in float4 units
    const size_t OFF2_4 = OFF1_4 + ((size_t)BVN * NEWN) / 4;
    #pragma unroll
    for (int iter = 0; iter < (BVN * SEGS) / (256 * 4); ++iter) {  // 4 iters
        const int idx = iter * 256 + t;                             // 0..1023
        const int c   = idx >> 2;                                   // 0..255
        const int sl4 = idx & 3;                                    // float4 chunk of s
        const int cb  = c & 3;                                      // c = v*B + b
        const int cv  = c >> 2;
        const int tc  = cb * 64 + cv;                               // thread-col of (b,v)
        float4 r;
        r.x = (float)srow[(sl4 * 4 + 0) * PITCH + tc];
        r.y = (float)srow[(sl4 * 4 + 1) * PITCH + tc];
        r.z = (float)srow[(sl4 * 4 + 2) * PITCH + tc];
        r.w = (float)srow[(sl4 * 4 + 3) * PITCH + tc];
        const size_t o4 = ((size_t)c * NEWN + (size_t)s0) / 4 + sl4;
        out4[OFF1_4 + o4] = r;
        const float fc = (float)c;
        out4[OFF2_4 + o4] = make_float4(fc, fc, fc, fc);
    }
}

extern "C" void kernel_launch(void* const* d_in, const int* in_sizes, int n_in,
                              void* d_out, int out_size) {
    const float* x       = (const float*)d_in[0];
    const float* weights = (const float*)d_in[1];
    const int*   row     = (const int*)d_in[2];
    const int*   col     = (const int*)d_in[3];
    float* out = (float*)d_out;

    pool_kernel<<<NEWN / SEGS, 256>>>(x, weights, row, col, out);
}